// round 1
// baseline (speedup 1.0000x reference)
#include <cuda_runtime.h>

// Problem constants (fixed shapes from reference)
#define IN_DIM  4096
#define OUT_DIM 4096
#define M_ROWS  16384   // B*S = 4*4096
#define N_ADP   8
#define RANK    64
#define K_FOLD  512     // N_ADP * RANK

// Scratch (static device globals — no runtime allocation)
__device__ float g_Weff[(size_t)OUT_DIM * IN_DIM];   // 64 MB
__device__ float g_U[(size_t)OUT_DIM * K_FOLD];      //  8 MB

// ---------------- packed fp32x2 helpers (Blackwell FFMA2 path) ----------------
__device__ __forceinline__ unsigned long long splat_f32x2(float x) {
    unsigned long long r;
    asm("mov.b64 %0, {%1, %1};" : "=l"(r) : "f"(x));
    return r;
}
__device__ __forceinline__ void fma_f32x2(unsigned long long& d,
                                          unsigned long long a,
                                          unsigned long long b) {
    asm("fma.rn.f32x2 %0, %1, %2, %0;" : "+l"(d) : "l"(a), "l"(b));
}
__device__ __forceinline__ void unpack_f32x2(unsigned long long v, float& lo, float& hi) {
    asm("mov.b64 {%0, %1}, %2;" : "=f"(lo), "=f"(hi) : "l"(v));
}

// ---------------- U[o, k] = ups[n,o,r] * mags[n,o] * scales[n] ----------------
__global__ void build_u_kernel(const float* __restrict__ ups,
                               const float* __restrict__ mags,
                               const float* __restrict__ scales) {
    int idx = blockIdx.x * blockDim.x + threadIdx.x;   // o*512 + k
    int o = idx >> 9;
    int k = idx & 511;
    int n = k >> 6;
    int r = k & 63;
    g_U[idx] = ups[((size_t)n * OUT_DIM + o) * RANK + r]
             * mags[n * OUT_DIM + o] * scales[n];
}

// ---------------- generic 128x128x16 fp32x2 GEMM ----------------
// C[m][n] = sum_k A[m][k] * Bop[n][k]  (+ Cadd[m][n]) (+ bias[n])
//   BT = true : B stored [N][K] row-major (transpose-on-load, like A)
//   BT = false: B stored [K][N] row-major (direct copy)
template <bool BT, bool ADD_C, bool ADD_BIAS>
__global__ __launch_bounds__(256)
void gemm_f32x2_kernel(const float* __restrict__ A,
                       const float* __restrict__ B,
                       const float* __restrict__ Cadd,
                       const float* __restrict__ bias,
                       float* __restrict__ C,
                       int M, int N, int K) {
    constexpr int BM = 128, BN = 128, BK = 16, LDSH = 132;  // +4 pad: bank spread
    __shared__ float As[2][BK][LDSH];
    __shared__ float Bs[2][BK][LDSH];

    const int tid = threadIdx.x;
    const int bm  = blockIdx.y * BM;
    const int bn  = blockIdx.x * BN;
    const int tx  = tid & 15;   // column group (cols tx*4.. and 64+tx*4..)
    const int ty  = tid >> 4;   // row group    (rows ty*4.. and 64+ty*4..)

    // global A-tile load: each thread 2x float4 along K, rows a_row / a_row+64
    const int a_row = tid >> 2;            // 0..63
    const int a_col = (tid & 3) << 2;      // 0,4,8,12
    const float* Abase = A + (size_t)(bm + a_row) * K + a_col;

    const float* Bbase;
    int b_k = 0, b_n = 0;
    if (BT) {
        Bbase = B + (size_t)(bn + a_row) * K + a_col;
    } else {
        b_k = tid >> 5;                    // 0..7  (and +8)
        b_n = (tid & 31) << 2;             // 0..124
        Bbase = B + (size_t)b_k * N + bn + b_n;
    }

    unsigned long long acc[4][8];          // 4 row-pairs x 8 cols
#pragma unroll
    for (int i = 0; i < 4; i++)
#pragma unroll
        for (int j = 0; j < 8; j++) acc[i][j] = 0ULL;

    const int nk = K / BK;
    float4 va0, va1, vb0, vb1;

    // prologue: tile 0 -> buffer 0
    va0 = *(const float4*)(Abase);
    va1 = *(const float4*)(Abase + (size_t)64 * K);
    if (BT) {
        vb0 = *(const float4*)(Bbase);
        vb1 = *(const float4*)(Bbase + (size_t)64 * K);
    } else {
        vb0 = *(const float4*)(Bbase);
        vb1 = *(const float4*)(Bbase + (size_t)8 * N);
    }
    {
        const float* pa0 = &va0.x; const float* pa1 = &va1.x;
#pragma unroll
        for (int j = 0; j < 4; j++) {
            As[0][a_col + j][a_row]      = pa0[j];
            As[0][a_col + j][a_row + 64] = pa1[j];
        }
        if (BT) {
            const float* pb0 = &vb0.x; const float* pb1 = &vb1.x;
#pragma unroll
            for (int j = 0; j < 4; j++) {
                Bs[0][a_col + j][a_row]      = pb0[j];
                Bs[0][a_col + j][a_row + 64] = pb1[j];
            }
        } else {
            *(float4*)&Bs[0][b_k][b_n]     = vb0;
            *(float4*)&Bs[0][b_k + 8][b_n] = vb1;
        }
    }
    __syncthreads();

    for (int t = 0; t < nk; ++t) {
        const int buf = t & 1;
        const bool has_next = (t + 1) < nk;

        if (has_next) {   // global -> reg prefetch of next tile
            const int k0 = (t + 1) * BK;
            va0 = *(const float4*)(Abase + k0);
            va1 = *(const float4*)(Abase + (size_t)64 * K + k0);
            if (BT) {
                vb0 = *(const float4*)(Bbase + k0);
                vb1 = *(const float4*)(Bbase + (size_t)64 * K + k0);
            } else {
                vb0 = *(const float4*)(Bbase + (size_t)k0 * N);
                vb1 = *(const float4*)(Bbase + (size_t)(k0 + 8) * N);
            }
        }

#pragma unroll
        for (int k = 0; k < BK; k++) {
            // A row-pairs come out of smem already packed (consecutive m)
            ulonglong2 a01 = *(const ulonglong2*)&As[buf][k][(ty << 2)];
            ulonglong2 a23 = *(const ulonglong2*)&As[buf][k][64 + (ty << 2)];
            float4 b0 = *(const float4*)&Bs[buf][k][(tx << 2)];
            float4 b1 = *(const float4*)&Bs[buf][k][64 + (tx << 2)];
            unsigned long long sb[8];
            sb[0] = splat_f32x2(b0.x); sb[1] = splat_f32x2(b0.y);
            sb[2] = splat_f32x2(b0.z); sb[3] = splat_f32x2(b0.w);
            sb[4] = splat_f32x2(b1.x); sb[5] = splat_f32x2(b1.y);
            sb[6] = splat_f32x2(b1.z); sb[7] = splat_f32x2(b1.w);
#pragma unroll
            for (int c = 0; c < 8; c++) {
                fma_f32x2(acc[0][c], a01.x, sb[c]);
                fma_f32x2(acc[1][c], a01.y, sb[c]);
                fma_f32x2(acc[2][c], a23.x, sb[c]);
                fma_f32x2(acc[3][c], a23.y, sb[c]);
            }
        }

        if (has_next) {   // reg -> smem (other buffer), then barrier
            const int nb = buf ^ 1;
            const float* pa0 = &va0.x; const float* pa1 = &va1.x;
#pragma unroll
            for (int j = 0; j < 4; j++) {
                As[nb][a_col + j][a_row]      = pa0[j];
                As[nb][a_col + j][a_row + 64] = pa1[j];
            }
            if (BT) {
                const float* pb0 = &vb0.x; const float* pb1 = &vb1.x;
#pragma unroll
                for (int j = 0; j < 4; j++) {
                    Bs[nb][a_col + j][a_row]      = pb0[j];
                    Bs[nb][a_col + j][a_row + 64] = pb1[j];
                }
            } else {
                *(float4*)&Bs[nb][b_k][b_n]     = vb0;
                *(float4*)&Bs[nb][b_k + 8][b_n] = vb1;
            }
            __syncthreads();
        }
    }

    // epilogue
    float res[8][8];
#pragma unroll
    for (int rp = 0; rp < 4; rp++)
#pragma unroll
        for (int c = 0; c < 8; c++)
            unpack_f32x2(acc[rp][c], res[2 * rp][c], res[2 * rp + 1][c]);

    const int c0 = bn + (tx << 2);
    const int c1 = c0 + 64;
    float4 bias0 = make_float4(0.f, 0.f, 0.f, 0.f);
    float4 bias1 = make_float4(0.f, 0.f, 0.f, 0.f);
    if (ADD_BIAS) {
        bias0 = *(const float4*)(bias + c0);
        bias1 = *(const float4*)(bias + c1);
    }

#pragma unroll
    for (int ri = 0; ri < 8; ++ri) {
        const int row = bm + ((ri < 4) ? ((ty << 2) + ri) : (64 + (ty << 2) + ri - 4));
        float4 v0 = make_float4(res[ri][0], res[ri][1], res[ri][2], res[ri][3]);
        float4 v1 = make_float4(res[ri][4], res[ri][5], res[ri][6], res[ri][7]);
        if (ADD_BIAS) {
            v0.x += bias0.x; v0.y += bias0.y; v0.z += bias0.z; v0.w += bias0.w;
            v1.x += bias1.x; v1.y += bias1.y; v1.z += bias1.z; v1.w += bias1.w;
        }
        if (ADD_C) {
            float4 w0 = *(const float4*)(Cadd + (size_t)row * N + c0);
            float4 w1 = *(const float4*)(Cadd + (size_t)row * N + c1);
            v0.x += w0.x; v0.y += w0.y; v0.z += w0.z; v0.w += w0.w;
            v1.x += w1.x; v1.y += w1.y; v1.z += w1.z; v1.w += w1.w;
        }
        *(float4*)(C + (size_t)row * N + c0) = v0;
        *(float4*)(C + (size_t)row * N + c1) = v1;
    }
}

// ---------------- launch ----------------
extern "C" void kernel_launch(void* const* d_in, const int* in_sizes, int n_in,
                              void* d_out, int out_size) {
    const float* x      = (const float*)d_in[0];
    const float* W      = (const float*)d_in[1];
    const float* b      = (const float*)d_in[2];
    const float* downs  = (const float*)d_in[3];
    const float* ups    = (const float*)d_in[4];
    const float* mags   = (const float*)d_in[5];
    const float* scales = (const float*)d_in[6];
    float* out = (float*)d_out;

    float* Weff = nullptr;
    float* U    = nullptr;
    cudaGetSymbolAddress((void**)&Weff, g_Weff);
    cudaGetSymbolAddress((void**)&U, g_U);

    // 1) scaled-up projection matrix U [OUT, 512]
    build_u_kernel<<<(OUT_DIM * K_FOLD) / 256, 256>>>(ups, mags, scales);

    // 2) W_eff = W + U @ downs    (downs is [512, IN] row-major = [K][N])
    dim3 gFold(OUT_DIM / 128, OUT_DIM / 128);
    gemm_f32x2_kernel<false, true, false><<<gFold, 256>>>(
        U, downs, W, nullptr, Weff, OUT_DIM, IN_DIM, K_FOLD);

    // 3) out = x @ W_eff^T + b    (W_eff is [OUT, IN] = [N][K])
    dim3 gMain(OUT_DIM / 128, M_ROWS / 128);
    gemm_f32x2_kernel<true, false, true><<<gMain, 256>>>(
        x, Weff, nullptr, b, out, M_ROWS, OUT_DIM, IN_DIM);
}

// round 3
// speedup vs baseline: 1.5434x; 1.5434x over previous
#include <cuda_runtime.h>
#include <cuda_bf16.h>
#include <cstdint>

// ---------------- problem constants ----------------
#define MTOT 16384      // B*S
#define NTOT 4096       // OUT
#define KTOT 4096       // IN
#define KF   512        // N_ADP * RANK
#define RANK 64

// ---------------- device scratch (static; no runtime alloc) ----------------
__device__ __nv_bfloat16 g_xh[(size_t)MTOT * KTOT];
__device__ __nv_bfloat16 g_xl[(size_t)MTOT * KTOT];
__device__ __nv_bfloat16 g_wh[(size_t)NTOT * KTOT];
__device__ __nv_bfloat16 g_wl[(size_t)NTOT * KTOT];
__device__ __nv_bfloat16 g_uh[(size_t)NTOT * KF];
__device__ __nv_bfloat16 g_ul[(size_t)NTOT * KF];
__device__ __nv_bfloat16 g_dh[(size_t)KTOT * KF];   // downs^T hi  [IN][KF]
__device__ __nv_bfloat16 g_dl[(size_t)KTOT * KF];   // downs^T lo

// ---------------- helpers ----------------
__device__ __forceinline__ void split2(float v, __nv_bfloat16& h, __nv_bfloat16& l) {
    h = __float2bfloat16(v);
    l = __float2bfloat16(v - __bfloat162float(h));
}
__device__ __forceinline__ uint32_t smem_u32(const void* p) {
    uint32_t a;
    asm("{ .reg .u64 t; cvta.to.shared.u64 t, %1; cvt.u32.u64 %0, t; }" : "=r"(a) : "l"(p));
    return a;
}
__device__ __forceinline__ void cp16(uint32_t dst, const void* src) {
    asm volatile("cp.async.cg.shared.global [%0], [%1], 16;" :: "r"(dst), "l"(src));
}
#define CP_COMMIT()  asm volatile("cp.async.commit_group;" ::: "memory")
#define CP_WAIT1()   asm volatile("cp.async.wait_group 1;" ::: "memory")

__device__ __forceinline__ void ldsm4(uint32_t r[4], uint32_t addr) {
    asm volatile("ldmatrix.sync.aligned.m8n8.x4.shared.b16 {%0,%1,%2,%3}, [%4];"
                 : "=r"(r[0]), "=r"(r[1]), "=r"(r[2]), "=r"(r[3]) : "r"(addr));
}
__device__ __forceinline__ void mma16816(float c[4], const uint32_t a[4], const uint32_t b0,
                                         const uint32_t b1) {
    asm volatile(
        "mma.sync.aligned.m16n8k16.row.col.f32.bf16.bf16.f32 "
        "{%0,%1,%2,%3}, {%4,%5,%6,%7}, {%8,%9}, {%0,%1,%2,%3};"
        : "+f"(c[0]), "+f"(c[1]), "+f"(c[2]), "+f"(c[3])
        : "r"(a[0]), "r"(a[1]), "r"(a[2]), "r"(a[3]), "r"(b0), "r"(b1));
}

// ---------------- prep kernels ----------------
__global__ void build_u_split(const float* __restrict__ ups,
                              const float* __restrict__ mags,
                              const float* __restrict__ scales) {
    int idx = blockIdx.x * blockDim.x + threadIdx.x;
    int o = idx >> 9;
    int k = idx & 511;
    int n = k >> 6;
    int r = k & 63;
    float v = ups[((size_t)n * NTOT + o) * RANK + r] * mags[n * NTOT + o] * scales[n];
    split2(v, g_uh[idx], g_ul[idx]);
}

__global__ void split_downsT(const float* __restrict__ downs) {
    __shared__ float t[32][33];
    const int i0 = blockIdx.x * 32;
    const int k0 = blockIdx.y * 32;
    const int tx = threadIdx.x & 31;
    const int ty = threadIdx.x >> 5;
#pragma unroll
    for (int r = 0; r < 4; r++) {
        int kr = ty + r * 8;
        t[kr][tx] = downs[(size_t)(k0 + kr) * KTOT + i0 + tx];
    }
    __syncthreads();
#pragma unroll
    for (int r = 0; r < 4; r++) {
        int ir = ty + r * 8;
        __nv_bfloat16 h, l;
        split2(t[tx][ir], h, l);
        g_dh[(size_t)(i0 + ir) * KF + k0 + tx] = h;
        g_dl[(size_t)(i0 + ir) * KF + k0 + tx] = l;
    }
}

__global__ void split_x(const float* __restrict__ x) {
    size_t i = ((size_t)blockIdx.x * blockDim.x + threadIdx.x) * 8;
    float4 a = *(const float4*)(x + i);
    float4 c = *(const float4*)(x + i + 4);
    float vs[8] = {a.x, a.y, a.z, a.w, c.x, c.y, c.z, c.w};
    unsigned short hs[8], ls[8];
#pragma unroll
    for (int j = 0; j < 8; j++) {
        __nv_bfloat16 h, l;
        split2(vs[j], h, l);
        hs[j] = __bfloat16_as_ushort(h);
        ls[j] = __bfloat16_as_ushort(l);
    }
    uint4 hv, lv;
    hv.x = hs[0] | ((uint32_t)hs[1] << 16); hv.y = hs[2] | ((uint32_t)hs[3] << 16);
    hv.z = hs[4] | ((uint32_t)hs[5] << 16); hv.w = hs[6] | ((uint32_t)hs[7] << 16);
    lv.x = ls[0] | ((uint32_t)ls[1] << 16); lv.y = ls[2] | ((uint32_t)ls[3] << 16);
    lv.z = ls[4] | ((uint32_t)ls[5] << 16); lv.w = ls[6] | ((uint32_t)ls[7] << 16);
    *(uint4*)((char*)g_xh + i * 2) = hv;
    *(uint4*)((char*)g_xl + i * 2) = lv;
}

// ---------------- HMMA GEMM: 3-term bf16 hi/lo compensated ----------------
// C = Ah.Bh^T + Ah.Bl^T + Al.Bh^T  (A: [M][K], B: [4096][K], both K-major)
// MODE 0: outf = C + add[n]            (bias)
// MODE 1: v = C + add[m*4096+n]; (outh,outl) = bf16 split of v
#define BM 256
#define BN 128
#define BK 32
#define STAGES 3
#define ASTAGE (BM * 128)                 // hi+lo interleaved: 128 B per row
#define BSTAGE (BN * 128)
#define STAGE_BYTES (ASTAGE + BSTAGE)     // 49152
#define SMEM_BYTES (STAGES * STAGE_BYTES) // 147456

template <int MODE>
__global__ __launch_bounds__(256, 1)
void gemm_mma(const __nv_bfloat16* __restrict__ Ah, const __nv_bfloat16* __restrict__ Al,
              const __nv_bfloat16* __restrict__ Bh, const __nv_bfloat16* __restrict__ Bl,
              const float* __restrict__ add,
              float* __restrict__ outf,
              __nv_bfloat16* __restrict__ outh, __nv_bfloat16* __restrict__ outl,
              int K) {
    extern __shared__ char smem[];
    const uint32_t sbase = smem_u32(smem);
    const int tid  = threadIdx.x;
    const int lane = tid & 31;
    const int wid  = tid >> 5;
    const int wm   = wid & 3;        // 0..3  (m tile of 64)
    const int wn   = wid >> 2;       // 0..1  (n tile of 64)
    const int bm   = blockIdx.y * BM;
    const int bn   = blockIdx.x * BN;
    const int nstage = K / BK;

    // ---- stage loader (cp.async) ----
    // A: thread tid handles row tid (8 chunks of 16B: 4 hi + 4 lo)
    // B: thread tid handles row tid>>1, chunks [(tid&1)*4 .. +4)
    const int arow = tid;
    const int brow = tid >> 1;
    const int bj0  = (tid & 1) * 4;
    const char* srcAh = (const char*)(Ah + (size_t)(bm + arow) * K);
    const char* srcAl = (const char*)(Al + (size_t)(bm + arow) * K);
    const char* srcBh = (const char*)(Bh + (size_t)(bn + brow) * K);
    const char* srcBl = (const char*)(Bl + (size_t)(bn + brow) * K);
    const int axor = arow & 7;
    const int bxor = brow & 7;

    auto load_stage = [&](int s, int k0) {
        const uint32_t sA = sbase + (uint32_t)s * STAGE_BYTES;
        const uint32_t sB = sA + ASTAGE;
        const uint32_t adst = sA + (uint32_t)arow * 128;
#pragma unroll
        for (int j = 0; j < 4; j++)
            cp16(adst + (uint32_t)((j ^ axor) << 4), srcAh + (size_t)(k0 + j * 8) * 2);
#pragma unroll
        for (int j = 0; j < 4; j++)
            cp16(adst + (uint32_t)(((j + 4) ^ axor) << 4), srcAl + (size_t)(k0 + j * 8) * 2);
        const uint32_t bdst = sB + (uint32_t)brow * 128;
#pragma unroll
        for (int jj = 0; jj < 2; jj++) {
            int j = bj0 + jj;                       // 0..3 or 4..7 split halves
            const char* s0 = (j < 4) ? srcBh : srcBl;
            int kc = (j & 3) * 8;
            cp16(bdst + (uint32_t)((j ^ bxor) << 4), s0 + (size_t)(k0 + kc) * 2);
            j += 2;
            s0 = (j < 4) ? srcBh : srcBl;
            kc = (j & 3) * 8;
            cp16(bdst + (uint32_t)((j ^ bxor) << 4), s0 + (size_t)(k0 + kc) * 2);
        }
    };

    float acc[4][8][4];
#pragma unroll
    for (int i = 0; i < 4; i++)
#pragma unroll
        for (int j = 0; j < 8; j++)
#pragma unroll
            for (int c = 0; c < 4; c++) acc[i][j][c] = 0.f;

    // prologue: stages 0 and 1
    load_stage(0, 0);
    CP_COMMIT();
    load_stage(1, BK);
    CP_COMMIT();

    // per-thread ldmatrix address components
    const int arowf  = wm * 64 + (lane & 15);   // A frag row (within BM), + mi*16
    const int ahalf  = lane >> 4;               // 0/1 -> k parity chunk
    const int browf  = wn * 64 + ((lane >> 4) << 3) + (lane & 7);  // B frag row, + p*16
    const int bpar   = (lane >> 3) & 1;

    for (int t = 0; t < nstage; ++t) {
        CP_WAIT1();
        __syncthreads();

        if (t + 2 < nstage) load_stage((t + 2) % STAGES, (t + 2) * BK);
        CP_COMMIT();

        const uint32_t sA = sbase + (uint32_t)((t % STAGES) * STAGE_BYTES);
        const uint32_t sB = sA + ASTAGE;

#pragma unroll
        for (int ks = 0; ks < 2; ++ks) {
            uint32_t ah[4][4], al[4][4], bh[8][2], bl[8][2];
#pragma unroll
            for (int mi = 0; mi < 4; ++mi) {
                int r = arowf + mi * 16;
                uint32_t base = sA + (uint32_t)r * 128;
                int ch = ks * 2 + ahalf;
                ldsm4(ah[mi], base + (uint32_t)((ch ^ (r & 7)) << 4));
                ch += 4;
                ldsm4(al[mi], base + (uint32_t)((ch ^ (r & 7)) << 4));
            }
#pragma unroll
            for (int p = 0; p < 4; ++p) {
                int r = browf + p * 16;
                uint32_t base = sB + (uint32_t)r * 128;
                int ch = ks * 2 + bpar;
                uint32_t tmp[4];
                ldsm4(tmp, base + (uint32_t)((ch ^ (r & 7)) << 4));
                bh[2 * p][0] = tmp[0]; bh[2 * p][1] = tmp[1];
                bh[2 * p + 1][0] = tmp[2]; bh[2 * p + 1][1] = tmp[3];
                ch += 4;
                ldsm4(tmp, base + (uint32_t)((ch ^ (r & 7)) << 4));
                bl[2 * p][0] = tmp[0]; bl[2 * p][1] = tmp[1];
                bl[2 * p + 1][0] = tmp[2]; bl[2 * p + 1][1] = tmp[3];
            }
#pragma unroll
            for (int mi = 0; mi < 4; ++mi)
#pragma unroll
                for (int nj = 0; nj < 8; ++nj) {
                    mma16816(acc[mi][nj], ah[mi], bh[nj][0], bh[nj][1]);
                    mma16816(acc[mi][nj], ah[mi], bl[nj][0], bl[nj][1]);
                    mma16816(acc[mi][nj], al[mi], bh[nj][0], bh[nj][1]);
                }
        }
        __syncthreads();
    }

    // ---- epilogue ----
    const int r0 = bm + wm * 64 + (lane >> 2);
    const int c0 = bn + wn * 64 + (lane & 3) * 2;
#pragma unroll
    for (int mi = 0; mi < 4; ++mi) {
#pragma unroll
        for (int nj = 0; nj < 8; ++nj) {
            int row = r0 + mi * 16;
            int col = c0 + nj * 8;
            if (MODE == 0) {
                float2 bv = *(const float2*)(add + col);
                float2 v0 = make_float2(acc[mi][nj][0] + bv.x, acc[mi][nj][1] + bv.y);
                float2 v1 = make_float2(acc[mi][nj][2] + bv.x, acc[mi][nj][3] + bv.y);
                *(float2*)(outf + (size_t)row * 4096 + col)       = v0;
                *(float2*)(outf + (size_t)(row + 8) * 4096 + col) = v1;
            } else {
                float2 w0 = *(const float2*)(add + (size_t)row * 4096 + col);
                float2 w1 = *(const float2*)(add + (size_t)(row + 8) * 4096 + col);
                float v00 = acc[mi][nj][0] + w0.x, v01 = acc[mi][nj][1] + w0.y;
                float v10 = acc[mi][nj][2] + w1.x, v11 = acc[mi][nj][3] + w1.y;
                __nv_bfloat16 h0, l0, h1, l1, h2, l2, h3, l3;
                split2(v00, h0, l0); split2(v01, h1, l1);
                split2(v10, h2, l2); split2(v11, h3, l3);
                uint32_t ph0 = __bfloat16_as_ushort(h0) | ((uint32_t)__bfloat16_as_ushort(h1) << 16);
                uint32_t pl0 = __bfloat16_as_ushort(l0) | ((uint32_t)__bfloat16_as_ushort(l1) << 16);
                uint32_t ph1 = __bfloat16_as_ushort(h2) | ((uint32_t)__bfloat16_as_ushort(h3) << 16);
                uint32_t pl1 = __bfloat16_as_ushort(l2) | ((uint32_t)__bfloat16_as_ushort(l3) << 16);
                *(uint32_t*)((char*)outh + ((size_t)row * 4096 + col) * 2)       = ph0;
                *(uint32_t*)((char*)outl + ((size_t)row * 4096 + col) * 2)       = pl0;
                *(uint32_t*)((char*)outh + ((size_t)(row + 8) * 4096 + col) * 2) = ph1;
                *(uint32_t*)((char*)outl + ((size_t)(row + 8) * 4096 + col) * 2) = pl1;
            }
        }
    }
}

// ---------------- launch ----------------
extern "C" void kernel_launch(void* const* d_in, const int* in_sizes, int n_in,
                              void* d_out, int out_size) {
    const float* x      = (const float*)d_in[0];
    const float* W      = (const float*)d_in[1];
    const float* b      = (const float*)d_in[2];
    const float* downs  = (const float*)d_in[3];
    const float* ups    = (const float*)d_in[4];
    const float* mags   = (const float*)d_in[5];
    const float* scales = (const float*)d_in[6];
    float* out = (float*)d_out;

    __nv_bfloat16 *xh, *xl, *wh, *wl, *uh, *ul, *dh, *dl;
    cudaGetSymbolAddress((void**)&xh, g_xh);
    cudaGetSymbolAddress((void**)&xl, g_xl);
    cudaGetSymbolAddress((void**)&wh, g_wh);
    cudaGetSymbolAddress((void**)&wl, g_wl);
    cudaGetSymbolAddress((void**)&uh, g_uh);
    cudaGetSymbolAddress((void**)&ul, g_ul);
    cudaGetSymbolAddress((void**)&dh, g_dh);
    cudaGetSymbolAddress((void**)&dl, g_dl);

    cudaFuncSetAttribute(gemm_mma<0>, cudaFuncAttributeMaxDynamicSharedMemorySize, SMEM_BYTES);
    cudaFuncSetAttribute(gemm_mma<1>, cudaFuncAttributeMaxDynamicSharedMemorySize, SMEM_BYTES);

    // 1) prep
    build_u_split<<<(NTOT * KF) / 256, 256>>>(ups, mags, scales);
    split_downsT<<<dim3(KTOT / 32, KF / 32), 256>>>(downs);
    split_x<<<(size_t)MTOT * KTOT / 8 / 256, 256>>>(x);

    // 2) fold: Weff = W + Uh.dT_h + Uh.dT_l + Ul.dT_h  -> (wh, wl)
    gemm_mma<1><<<dim3(NTOT / BN, NTOT / BM), 256, SMEM_BYTES>>>(
        uh, ul, dh, dl, W, nullptr, wh, wl, KF);

    // 3) main: out = Xh.Wh + Xh.Wl + Xl.Wh + bias
    gemm_mma<0><<<dim3(NTOT / BN, MTOT / BM), 256, SMEM_BYTES>>>(
        xh, xl, wh, wl, b, out, nullptr, nullptr, KTOT);
}

// round 6
// speedup vs baseline: 1.5453x; 1.0012x over previous
#include <cuda_runtime.h>
#include <cuda_bf16.h>
#include <cstdint>

// ---------------- problem constants ----------------
#define MTOT 16384      // B*S
#define NTOT 4096       // OUT
#define KTOT 4096       // IN
#define KF   512        // N_ADP * RANK
#define RANK 64

// ---------------- device scratch (static; no runtime alloc) ----------------
__device__ __nv_bfloat16 g_xh[(size_t)MTOT * KTOT];
__device__ __nv_bfloat16 g_xl[(size_t)MTOT * KTOT];
__device__ __nv_bfloat16 g_wh[(size_t)NTOT * KTOT];
__device__ __nv_bfloat16 g_wl[(size_t)NTOT * KTOT];
__device__ __nv_bfloat16 g_uh[(size_t)NTOT * KF];
__device__ __nv_bfloat16 g_ul[(size_t)NTOT * KF];
__device__ __nv_bfloat16 g_dh[(size_t)KTOT * KF];   // downs^T hi  [IN][KF]
__device__ __nv_bfloat16 g_dl[(size_t)KTOT * KF];   // downs^T lo

// ---------------- helpers ----------------
__device__ __forceinline__ void split2(float v, __nv_bfloat16& h, __nv_bfloat16& l) {
    h = __float2bfloat16(v);
    l = __float2bfloat16(v - __bfloat162float(h));
}
__device__ __forceinline__ uint32_t smem_u32(const void* p) {
    uint32_t a;
    asm("{ .reg .u64 t; cvta.to.shared.u64 t, %1; cvt.u32.u64 %0, t; }" : "=r"(a) : "l"(p));
    return a;
}
__device__ __forceinline__ void cp16(uint32_t dst, const void* src) {
    asm volatile("cp.async.cg.shared.global [%0], [%1], 16;" :: "r"(dst), "l"(src));
}
#define CP_COMMIT()  asm volatile("cp.async.commit_group;" ::: "memory")
#define CP_WAIT2()   asm volatile("cp.async.wait_group 2;" ::: "memory")

__device__ __forceinline__ void ldsm4(uint32_t r[4], uint32_t addr) {
    asm volatile("ldmatrix.sync.aligned.m8n8.x4.shared.b16 {%0,%1,%2,%3}, [%4];"
                 : "=r"(r[0]), "=r"(r[1]), "=r"(r[2]), "=r"(r[3]) : "r"(addr));
}
__device__ __forceinline__ void mma16816(float c[4], const uint32_t a[4], const uint32_t b0,
                                         const uint32_t b1) {
    asm volatile(
        "mma.sync.aligned.m16n8k16.row.col.f32.bf16.bf16.f32 "
        "{%0,%1,%2,%3}, {%4,%5,%6,%7}, {%8,%9}, {%0,%1,%2,%3};"
        : "+f"(c[0]), "+f"(c[1]), "+f"(c[2]), "+f"(c[3])
        : "r"(a[0]), "r"(a[1]), "r"(a[2]), "r"(a[3]), "r"(b0), "r"(b1));
}

// ---------------- prep kernels ----------------
__global__ void build_u_split(const float* __restrict__ ups,
                              const float* __restrict__ mags,
                              const float* __restrict__ scales) {
    int idx = blockIdx.x * blockDim.x + threadIdx.x;
    int o = idx >> 9;
    int k = idx & 511;
    int n = k >> 6;
    int r = k & 63;
    float v = ups[((size_t)n * NTOT + o) * RANK + r] * mags[n * NTOT + o] * scales[n];
    split2(v, g_uh[idx], g_ul[idx]);
}

__global__ void split_downsT(const float* __restrict__ downs) {
    __shared__ float t[32][33];
    const int i0 = blockIdx.x * 32;
    const int k0 = blockIdx.y * 32;
    const int tx = threadIdx.x & 31;
    const int ty = threadIdx.x >> 5;
#pragma unroll
    for (int r = 0; r < 4; r++) {
        int kr = ty + r * 8;
        t[kr][tx] = downs[(size_t)(k0 + kr) * KTOT + i0 + tx];
    }
    __syncthreads();
#pragma unroll
    for (int r = 0; r < 4; r++) {
        int ir = ty + r * 8;
        __nv_bfloat16 h, l;
        split2(t[tx][ir], h, l);
        g_dh[(size_t)(i0 + ir) * KF + k0 + tx] = h;
        g_dl[(size_t)(i0 + ir) * KF + k0 + tx] = l;
    }
}

__global__ void split_x(const float* __restrict__ x) {
    size_t i = ((size_t)blockIdx.x * blockDim.x + threadIdx.x) * 8;
    float4 a = *(const float4*)(x + i);
    float4 c = *(const float4*)(x + i + 4);
    float vs[8] = {a.x, a.y, a.z, a.w, c.x, c.y, c.z, c.w};
    unsigned short hs[8], ls[8];
#pragma unroll
    for (int j = 0; j < 8; j++) {
        __nv_bfloat16 h, l;
        split2(vs[j], h, l);
        hs[j] = __bfloat16_as_ushort(h);
        ls[j] = __bfloat16_as_ushort(l);
    }
    uint4 hv, lv;
    hv.x = hs[0] | ((uint32_t)hs[1] << 16); hv.y = hs[2] | ((uint32_t)hs[3] << 16);
    hv.z = hs[4] | ((uint32_t)hs[5] << 16); hv.w = hs[6] | ((uint32_t)hs[7] << 16);
    lv.x = ls[0] | ((uint32_t)ls[1] << 16); lv.y = ls[2] | ((uint32_t)ls[3] << 16);
    lv.z = ls[4] | ((uint32_t)ls[5] << 16); lv.w = ls[6] | ((uint32_t)ls[7] << 16);
    *(uint4*)((char*)g_xh + i * 2) = hv;
    *(uint4*)((char*)g_xl + i * 2) = lv;
}

// ---------------- HMMA GEMM: 3-term bf16 hi/lo compensated ----------------
// C = Ah.Bh^T + Ah.Bl^T + Al.Bh^T  (A: [M][K], B: [4096][K], both K-major)
// MODE 0: outf = C + add[n]            (bias)
// MODE 1: v = C + add[m*4096+n]; (outh,outl) = bf16 split of v
#define BM 256
#define BN 128
#define BK 32
#define STAGES 4
#define ASTAGE (BM * 128)                 // hi+lo interleaved: 128 B per row
#define BSTAGE (BN * 128)
#define STAGE_BYTES (ASTAGE + BSTAGE)     // 49152
#define SMEM_BYTES (STAGES * STAGE_BYTES) // 196608

template <int MODE>
__global__ __launch_bounds__(256, 1)
void gemm_mma(const __nv_bfloat16* __restrict__ Ah, const __nv_bfloat16* __restrict__ Al,
              const __nv_bfloat16* __restrict__ Bh, const __nv_bfloat16* __restrict__ Bl,
              const float* __restrict__ add,
              float* __restrict__ outf,
              __nv_bfloat16* __restrict__ outh, __nv_bfloat16* __restrict__ outl,
              int K) {
    extern __shared__ char smem[];
    const uint32_t sbase = smem_u32(smem);
    const int tid  = threadIdx.x;
    const int lane = tid & 31;
    const int wid  = tid >> 5;
    const int wm   = wid & 3;        // 0..3  (m tile of 64)
    const int wn   = wid >> 2;       // 0..1  (n tile of 64)
    const int bm   = blockIdx.y * BM;
    const int bn   = blockIdx.x * BN;
    const int nstage = K / BK;

    // ---- stage loader (cp.async) ----
    const int arow = tid;
    const int brow = tid >> 1;
    const int bj0  = (tid & 1) * 4;
    const char* srcAh = (const char*)(Ah + (size_t)(bm + arow) * K);
    const char* srcAl = (const char*)(Al + (size_t)(bm + arow) * K);
    const char* srcBh = (const char*)(Bh + (size_t)(bn + brow) * K);
    const char* srcBl = (const char*)(Bl + (size_t)(bn + brow) * K);
    const int axor = arow & 7;
    const int bxor = brow & 7;

    auto load_stage = [&](int s, int k0) {
        const uint32_t sA = sbase + (uint32_t)s * STAGE_BYTES;
        const uint32_t sB = sA + ASTAGE;
        const uint32_t adst = sA + (uint32_t)arow * 128;
#pragma unroll
        for (int j = 0; j < 4; j++)
            cp16(adst + (uint32_t)((j ^ axor) << 4), srcAh + (size_t)(k0 + j * 8) * 2);
#pragma unroll
        for (int j = 0; j < 4; j++)
            cp16(adst + (uint32_t)(((j + 4) ^ axor) << 4), srcAl + (size_t)(k0 + j * 8) * 2);
        const uint32_t bdst = sB + (uint32_t)brow * 128;
#pragma unroll
        for (int jj = 0; jj < 2; jj++) {
            int j = bj0 + jj;
            const char* s0 = (j < 4) ? srcBh : srcBl;
            int kc = (j & 3) * 8;
            cp16(bdst + (uint32_t)((j ^ bxor) << 4), s0 + (size_t)(k0 + kc) * 2);
            j += 2;
            s0 = (j < 4) ? srcBh : srcBl;
            kc = (j & 3) * 8;
            cp16(bdst + (uint32_t)((j ^ bxor) << 4), s0 + (size_t)(k0 + kc) * 2);
        }
    };

    float acc[4][8][4];
#pragma unroll
    for (int i = 0; i < 4; i++)
#pragma unroll
        for (int j = 0; j < 8; j++)
#pragma unroll
            for (int c = 0; c < 4; c++) acc[i][j][c] = 0.f;

    // prologue: stages 0..2
    load_stage(0, 0);
    CP_COMMIT();
    load_stage(1, BK);
    CP_COMMIT();
    load_stage(2, 2 * BK);
    CP_COMMIT();

    // per-thread ldmatrix address components
    const int arowf = wm * 64 + (lane & 15);                       // + mi*16
    const int ahalf = lane >> 4;                                   // k parity chunk
    const int browf = wn * 64 + ((lane >> 4) << 3) + (lane & 7);   // + p*16
    const int bpar  = (lane >> 3) & 1;

    for (int t = 0; t < nstage; ++t) {
        CP_WAIT2();
        __syncthreads();

        if (t + 3 < nstage) load_stage((t + 3) % STAGES, (t + 3) * BK);
        CP_COMMIT();

        const uint32_t sA = sbase + (uint32_t)((t % STAGES) * STAGE_BYTES);
        const uint32_t sB = sA + ASTAGE;

#pragma unroll
        for (int ks = 0; ks < 2; ++ks) {
            uint32_t ah[4][4], al[4][4];
#pragma unroll
            for (int mi = 0; mi < 4; ++mi) {
                int r = arowf + mi * 16;
                uint32_t base = sA + (uint32_t)r * 128;
                int ch = ks * 2 + ahalf;
                ldsm4(ah[mi], base + (uint32_t)((ch ^ (r & 7)) << 4));
                ldsm4(al[mi], base + (uint32_t)(((ch + 4) ^ (r & 7)) << 4));
            }
#pragma unroll
            for (int p = 0; p < 4; ++p) {
                int r = browf + p * 16;
                uint32_t base = sB + (uint32_t)r * 128;
                int ch = ks * 2 + bpar;
                uint32_t bh[4], bl[4];
                ldsm4(bh, base + (uint32_t)((ch ^ (r & 7)) << 4));
                ldsm4(bl, base + (uint32_t)(((ch + 4) ^ (r & 7)) << 4));
                const int n0 = 2 * p, n1 = 2 * p + 1;
                // term-major ordering: 8 independent HMMAs between acc reuses
#pragma unroll
                for (int mi = 0; mi < 4; ++mi) {
                    mma16816(acc[mi][n0], ah[mi], bh[0], bh[1]);
                    mma16816(acc[mi][n1], ah[mi], bh[2], bh[3]);
                }
#pragma unroll
                for (int mi = 0; mi < 4; ++mi) {
                    mma16816(acc[mi][n0], ah[mi], bl[0], bl[1]);
                    mma16816(acc[mi][n1], ah[mi], bl[2], bl[3]);
                }
#pragma unroll
                for (int mi = 0; mi < 4; ++mi) {
                    mma16816(acc[mi][n0], al[mi], bh[0], bh[1]);
                    mma16816(acc[mi][n1], al[mi], bh[2], bh[3]);
                }
            }
        }
        __syncthreads();
    }

    // ---- epilogue ----
    const int r0 = bm + wm * 64 + (lane >> 2);
    const int c0 = bn + wn * 64 + (lane & 3) * 2;
#pragma unroll
    for (int mi = 0; mi < 4; ++mi) {
#pragma unroll
        for (int nj = 0; nj < 8; ++nj) {
            int row = r0 + mi * 16;
            int col = c0 + nj * 8;
            if (MODE == 0) {
                float2 bv = *(const float2*)(add + col);
                float2 v0 = make_float2(acc[mi][nj][0] + bv.x, acc[mi][nj][1] + bv.y);
                float2 v1 = make_float2(acc[mi][nj][2] + bv.x, acc[mi][nj][3] + bv.y);
                *(float2*)(outf + (size_t)row * 4096 + col)       = v0;
                *(float2*)(outf + (size_t)(row + 8) * 4096 + col) = v1;
            } else {
                float2 w0 = *(const float2*)(add + (size_t)row * 4096 + col);
                float2 w1 = *(const float2*)(add + (size_t)(row + 8) * 4096 + col);
                float v00 = acc[mi][nj][0] + w0.x, v01 = acc[mi][nj][1] + w0.y;
                float v10 = acc[mi][nj][2] + w1.x, v11 = acc[mi][nj][3] + w1.y;
                __nv_bfloat16 h0, l0, h1, l1, h2, l2, h3, l3;
                split2(v00, h0, l0); split2(v01, h1, l1);
                split2(v10, h2, l2); split2(v11, h3, l3);
                uint32_t ph0 = __bfloat16_as_ushort(h0) | ((uint32_t)__bfloat16_as_ushort(h1) << 16);
                uint32_t pl0 = __bfloat16_as_ushort(l0) | ((uint32_t)__bfloat16_as_ushort(l1) << 16);
                uint32_t ph1 = __bfloat16_as_ushort(h2) | ((uint32_t)__bfloat16_as_ushort(h3) << 16);
                uint32_t pl1 = __bfloat16_as_ushort(l2) | ((uint32_t)__bfloat16_as_ushort(l3) << 16);
                *(uint32_t*)((char*)outh + ((size_t)row * 4096 + col) * 2)       = ph0;
                *(uint32_t*)((char*)outl + ((size_t)row * 4096 + col) * 2)       = pl0;
                *(uint32_t*)((char*)outh + ((size_t)(row + 8) * 4096 + col) * 2) = ph1;
                *(uint32_t*)((char*)outl + ((size_t)(row + 8) * 4096 + col) * 2) = pl1;
            }
        }
    }
}

// ---------------- launch ----------------
extern "C" void kernel_launch(void* const* d_in, const int* in_sizes, int n_in,
                              void* d_out, int out_size) {
    const float* x      = (const float*)d_in[0];
    const float* W      = (const float*)d_in[1];
    const float* b      = (const float*)d_in[2];
    const float* downs  = (const float*)d_in[3];
    const float* ups    = (const float*)d_in[4];
    const float* mags   = (const float*)d_in[5];
    const float* scales = (const float*)d_in[6];
    float* out = (float*)d_out;

    __nv_bfloat16 *xh, *xl, *wh, *wl, *uh, *ul, *dh, *dl;
    cudaGetSymbolAddress((void**)&xh, g_xh);
    cudaGetSymbolAddress((void**)&xl, g_xl);
    cudaGetSymbolAddress((void**)&wh, g_wh);
    cudaGetSymbolAddress((void**)&wl, g_wl);
    cudaGetSymbolAddress((void**)&uh, g_uh);
    cudaGetSymbolAddress((void**)&ul, g_ul);
    cudaGetSymbolAddress((void**)&dh, g_dh);
    cudaGetSymbolAddress((void**)&dl, g_dl);

    cudaFuncSetAttribute(gemm_mma<0>, cudaFuncAttributeMaxDynamicSharedMemorySize, SMEM_BYTES);
    cudaFuncSetAttribute(gemm_mma<1>, cudaFuncAttributeMaxDynamicSharedMemorySize, SMEM_BYTES);

    // 1) prep
    build_u_split<<<(NTOT * KF) / 256, 256>>>(ups, mags, scales);
    split_downsT<<<dim3(KTOT / 32, KF / 32), 256>>>(downs);
    split_x<<<(size_t)MTOT * KTOT / 8 / 256, 256>>>(x);

    // 2) fold: Weff = W + Uh.dT_h + Uh.dT_l + Ul.dT_h  -> (wh, wl)
    gemm_mma<1><<<dim3(NTOT / BN, NTOT / BM), 256, SMEM_BYTES>>>(
        uh, ul, dh, dl, W, nullptr, wh, wl, KF);

    // 3) main: out = Xh.Wh + Xh.Wl + Xl.Wh + bias
    gemm_mma<0><<<dim3(NTOT / BN, MTOT / BM), 256, SMEM_BYTES>>>(
        xh, xl, wh, wl, b, out, nullptr, nullptr, KTOT);
}

// round 7
// speedup vs baseline: 1.6544x; 1.0706x over previous
#include <cuda_runtime.h>
#include <cuda_bf16.h>
#include <cstdint>

// ---------------- problem constants ----------------
#define MTOT 16384      // B*S
#define NTOT 4096       // OUT
#define KTOT 4096       // IN
#define KF   512        // N_ADP * RANK
#define RANK 64

// ---------------- device scratch (static; no runtime alloc) ----------------
__device__ __nv_bfloat16 g_xh[(size_t)MTOT * KTOT];
__device__ __nv_bfloat16 g_xl[(size_t)MTOT * KTOT];
__device__ __nv_bfloat16 g_wh[(size_t)NTOT * KTOT];
__device__ __nv_bfloat16 g_wl[(size_t)NTOT * KTOT];
__device__ __nv_bfloat16 g_uh[(size_t)NTOT * KF];
__device__ __nv_bfloat16 g_ul[(size_t)NTOT * KF];
__device__ __nv_bfloat16 g_dh[(size_t)KTOT * KF];   // downs^T hi  [IN][KF]
__device__ __nv_bfloat16 g_dl[(size_t)KTOT * KF];   // downs^T lo

// ---------------- helpers ----------------
__device__ __forceinline__ void split2(float v, __nv_bfloat16& h, __nv_bfloat16& l) {
    h = __float2bfloat16(v);
    l = __float2bfloat16(v - __bfloat162float(h));
}
__device__ __forceinline__ uint32_t smem_u32(const void* p) {
    uint32_t a;
    asm("{ .reg .u64 t; cvta.to.shared.u64 t, %1; cvt.u32.u64 %0, t; }" : "=r"(a) : "l"(p));
    return a;
}
__device__ __forceinline__ void cp16(uint32_t dst, const void* src) {
    asm volatile("cp.async.cg.shared.global [%0], [%1], 16;" :: "r"(dst), "l"(src));
}
#define CP_COMMIT()  asm volatile("cp.async.commit_group;" ::: "memory")
#define CP_WAIT2()   asm volatile("cp.async.wait_group 2;" ::: "memory")

__device__ __forceinline__ void ldsm4(uint32_t r[4], uint32_t addr) {
    asm volatile("ldmatrix.sync.aligned.m8n8.x4.shared.b16 {%0,%1,%2,%3}, [%4];"
                 : "=r"(r[0]), "=r"(r[1]), "=r"(r[2]), "=r"(r[3]) : "r"(addr));
}
__device__ __forceinline__ void mma16816(float c[4], const uint32_t a[4], const uint32_t b0,
                                         const uint32_t b1) {
    asm volatile(
        "mma.sync.aligned.m16n8k16.row.col.f32.bf16.bf16.f32 "
        "{%0,%1,%2,%3}, {%4,%5,%6,%7}, {%8,%9}, {%0,%1,%2,%3};"
        : "+f"(c[0]), "+f"(c[1]), "+f"(c[2]), "+f"(c[3])
        : "r"(a[0]), "r"(a[1]), "r"(a[2]), "r"(a[3]), "r"(b0), "r"(b1));
}

// ---------------- prep kernels ----------------
__global__ void build_u_split(const float* __restrict__ ups,
                              const float* __restrict__ mags,
                              const float* __restrict__ scales) {
    int idx = blockIdx.x * blockDim.x + threadIdx.x;
    int o = idx >> 9;
    int k = idx & 511;
    int n = k >> 6;
    int r = k & 63;
    float v = ups[((size_t)n * NTOT + o) * RANK + r] * mags[n * NTOT + o] * scales[n];
    split2(v, g_uh[idx], g_ul[idx]);
}

__global__ void split_downsT(const float* __restrict__ downs) {
    __shared__ float t[32][33];
    const int i0 = blockIdx.x * 32;
    const int k0 = blockIdx.y * 32;
    const int tx = threadIdx.x & 31;
    const int ty = threadIdx.x >> 5;
#pragma unroll
    for (int r = 0; r < 4; r++) {
        int kr = ty + r * 8;
        t[kr][tx] = downs[(size_t)(k0 + kr) * KTOT + i0 + tx];
    }
    __syncthreads();
#pragma unroll
    for (int r = 0; r < 4; r++) {
        int ir = ty + r * 8;
        __nv_bfloat16 h, l;
        split2(t[tx][ir], h, l);
        g_dh[(size_t)(i0 + ir) * KF + k0 + tx] = h;
        g_dl[(size_t)(i0 + ir) * KF + k0 + tx] = l;
    }
}

__global__ void split_x(const float* __restrict__ x) {
    size_t i = ((size_t)blockIdx.x * blockDim.x + threadIdx.x) * 8;
    float4 a = *(const float4*)(x + i);
    float4 c = *(const float4*)(x + i + 4);
    float vs[8] = {a.x, a.y, a.z, a.w, c.x, c.y, c.z, c.w};
    unsigned short hs[8], ls[8];
#pragma unroll
    for (int j = 0; j < 8; j++) {
        __nv_bfloat16 h, l;
        split2(vs[j], h, l);
        hs[j] = __bfloat16_as_ushort(h);
        ls[j] = __bfloat16_as_ushort(l);
    }
    uint4 hv, lv;
    hv.x = hs[0] | ((uint32_t)hs[1] << 16); hv.y = hs[2] | ((uint32_t)hs[3] << 16);
    hv.z = hs[4] | ((uint32_t)hs[5] << 16); hv.w = hs[6] | ((uint32_t)hs[7] << 16);
    lv.x = ls[0] | ((uint32_t)ls[1] << 16); lv.y = ls[2] | ((uint32_t)ls[3] << 16);
    lv.z = ls[4] | ((uint32_t)ls[5] << 16); lv.w = ls[6] | ((uint32_t)ls[7] << 16);
    *(uint4*)((char*)g_xh + i * 2) = hv;
    *(uint4*)((char*)g_xl + i * 2) = lv;
}

// ---------------- HMMA GEMM: 3-term bf16 hi/lo compensated ----------------
// C = Ah.Bh^T + Ah.Bl^T + Al.Bh^T  (A: [M][K], B: [4096][K], both K-major)
// 512 threads, warp grid 4(m) x 4(n), warp tile 64x32
// MODE 0: outf = C + add[n]            (bias)
// MODE 1: v = C + add[m*4096+n]; (outh,outl) = bf16 split of v
#define BM 256
#define BN 128
#define BK 32
#define STAGES 4
#define ASTAGE (BM * 128)                 // hi+lo interleaved: 128 B per row
#define BSTAGE (BN * 128)
#define STAGE_BYTES (ASTAGE + BSTAGE)     // 49152
#define SMEM_BYTES (STAGES * STAGE_BYTES) // 196608

template <int MODE>
__global__ __launch_bounds__(512, 1)
void gemm_mma(const __nv_bfloat16* __restrict__ Ah, const __nv_bfloat16* __restrict__ Al,
              const __nv_bfloat16* __restrict__ Bh, const __nv_bfloat16* __restrict__ Bl,
              const float* __restrict__ add,
              float* __restrict__ outf,
              __nv_bfloat16* __restrict__ outh, __nv_bfloat16* __restrict__ outl,
              int K) {
    extern __shared__ char smem[];
    const uint32_t sbase = smem_u32(smem);
    const int tid  = threadIdx.x;
    const int lane = tid & 31;
    const int wid  = tid >> 5;       // 0..15
    const int wm   = wid & 3;        // m tile of 64
    const int wn   = wid >> 2;       // n tile of 32
    const int bm   = blockIdx.y * BM;
    const int bn   = blockIdx.x * BN;
    const int nstage = K / BK;

    // ---- stage loader (cp.async), 512 threads ----
    // A: thread -> row tid>>1, half (hi/lo) = tid&1, 4 chunks of 16B
    // B: thread -> row tid>>2, 2 chunks (of 8) = (tid&3)*2 ..
    const int arow = tid >> 1;
    const int ahlf = tid & 1;
    const int brow = tid >> 2;
    const int bj0  = (tid & 3) * 2;
    const char* srcA  = (const char*)((ahlf ? Al : Ah) + (size_t)(bm + arow) * K);
    const char* srcBh = (const char*)(Bh + (size_t)(bn + brow) * K);
    const char* srcBl = (const char*)(Bl + (size_t)(bn + brow) * K);
    const int axor = arow & 7;
    const int bxor = brow & 7;

    auto load_stage = [&](int s, int k0) {
        const uint32_t sA = sbase + (uint32_t)s * STAGE_BYTES;
        const uint32_t sB = sA + ASTAGE;
        const uint32_t adst = sA + (uint32_t)arow * 128;
#pragma unroll
        for (int j = 0; j < 4; j++) {
            int ch = ahlf * 4 + j;
            cp16(adst + (uint32_t)((ch ^ axor) << 4), srcA + (size_t)(k0 + j * 8) * 2);
        }
        const uint32_t bdst = sB + (uint32_t)brow * 128;
#pragma unroll
        for (int jj = 0; jj < 2; jj++) {
            int j = bj0 + jj;                       // 0..7
            const char* s0 = (j < 4) ? srcBh : srcBl;
            int kc = (j & 3) * 8;
            cp16(bdst + (uint32_t)((j ^ bxor) << 4), s0 + (size_t)(k0 + kc) * 2);
        }
    };

    float acc[4][4][4];
#pragma unroll
    for (int i = 0; i < 4; i++)
#pragma unroll
        for (int j = 0; j < 4; j++)
#pragma unroll
            for (int c = 0; c < 4; c++) acc[i][j][c] = 0.f;

    // prologue: stages 0..2
    load_stage(0, 0);
    CP_COMMIT();
    load_stage(1, BK);
    CP_COMMIT();
    load_stage(2, 2 * BK);
    CP_COMMIT();

    // per-thread ldmatrix address components
    const int arowf = wm * 64 + (lane & 15);                       // + mi*16
    const int ahalf = lane >> 4;                                   // k parity chunk
    const int browf = wn * 32 + ((lane >> 4) << 3) + (lane & 7);   // + p*16
    const int bpar  = (lane >> 3) & 1;

    for (int t = 0; t < nstage; ++t) {
        CP_WAIT2();
        __syncthreads();

        if (t + 3 < nstage) load_stage((t + 3) % STAGES, (t + 3) * BK);
        CP_COMMIT();

        const uint32_t sA = sbase + (uint32_t)((t % STAGES) * STAGE_BYTES);
        const uint32_t sB = sA + ASTAGE;

#pragma unroll
        for (int ks = 0; ks < 2; ++ks) {
            // B fragments for this warp's 32 columns (hi + lo)
            uint32_t bh[2][4], bl[2][4];
#pragma unroll
            for (int p = 0; p < 2; ++p) {
                int r = browf + p * 16;
                uint32_t base = sB + (uint32_t)r * 128;
                int ch = ks * 2 + bpar;
                ldsm4(bh[p], base + (uint32_t)((ch ^ (r & 7)) << 4));
                ldsm4(bl[p], base + (uint32_t)(((ch + 4) ^ (r & 7)) << 4));
            }
#pragma unroll
            for (int mi = 0; mi < 4; ++mi) {
                int r = arowf + mi * 16;
                uint32_t base = sA + (uint32_t)r * 128;
                int ch = ks * 2 + ahalf;
                uint32_t ah[4], al[4];
                ldsm4(ah, base + (uint32_t)((ch ^ (r & 7)) << 4));
                ldsm4(al, base + (uint32_t)(((ch + 4) ^ (r & 7)) << 4));
                // term-major: 4 independent HMMAs between reuses of each acc
                mma16816(acc[mi][0], ah, bh[0][0], bh[0][1]);
                mma16816(acc[mi][1], ah, bh[0][2], bh[0][3]);
                mma16816(acc[mi][2], ah, bh[1][0], bh[1][1]);
                mma16816(acc[mi][3], ah, bh[1][2], bh[1][3]);
                mma16816(acc[mi][0], ah, bl[0][0], bl[0][1]);
                mma16816(acc[mi][1], ah, bl[0][2], bl[0][3]);
                mma16816(acc[mi][2], ah, bl[1][0], bl[1][1]);
                mma16816(acc[mi][3], ah, bl[1][2], bl[1][3]);
                mma16816(acc[mi][0], al, bh[0][0], bh[0][1]);
                mma16816(acc[mi][1], al, bh[0][2], bh[0][3]);
                mma16816(acc[mi][2], al, bh[1][0], bh[1][1]);
                mma16816(acc[mi][3], al, bh[1][2], bh[1][3]);
            }
        }
        __syncthreads();
    }

    // ---- epilogue ----
    const int r0 = bm + wm * 64 + (lane >> 2);
    const int c0 = bn + wn * 32 + (lane & 3) * 2;
#pragma unroll
    for (int mi = 0; mi < 4; ++mi) {
#pragma unroll
        for (int nj = 0; nj < 4; ++nj) {
            int row = r0 + mi * 16;
            int col = c0 + nj * 8;
            if (MODE == 0) {
                float2 bv = *(const float2*)(add + col);
                float2 v0 = make_float2(acc[mi][nj][0] + bv.x, acc[mi][nj][1] + bv.y);
                float2 v1 = make_float2(acc[mi][nj][2] + bv.x, acc[mi][nj][3] + bv.y);
                *(float2*)(outf + (size_t)row * 4096 + col)       = v0;
                *(float2*)(outf + (size_t)(row + 8) * 4096 + col) = v1;
            } else {
                float2 w0 = *(const float2*)(add + (size_t)row * 4096 + col);
                float2 w1 = *(const float2*)(add + (size_t)(row + 8) * 4096 + col);
                float v00 = acc[mi][nj][0] + w0.x, v01 = acc[mi][nj][1] + w0.y;
                float v10 = acc[mi][nj][2] + w1.x, v11 = acc[mi][nj][3] + w1.y;
                __nv_bfloat16 h0, l0, h1, l1, h2, l2, h3, l3;
                split2(v00, h0, l0); split2(v01, h1, l1);
                split2(v10, h2, l2); split2(v11, h3, l3);
                uint32_t ph0 = __bfloat16_as_ushort(h0) | ((uint32_t)__bfloat16_as_ushort(h1) << 16);
                uint32_t pl0 = __bfloat16_as_ushort(l0) | ((uint32_t)__bfloat16_as_ushort(l1) << 16);
                uint32_t ph1 = __bfloat16_as_ushort(h2) | ((uint32_t)__bfloat16_as_ushort(h3) << 16);
                uint32_t pl1 = __bfloat16_as_ushort(l2) | ((uint32_t)__bfloat16_as_ushort(l3) << 16);
                *(uint32_t*)((char*)outh + ((size_t)row * 4096 + col) * 2)       = ph0;
                *(uint32_t*)((char*)outl + ((size_t)row * 4096 + col) * 2)       = pl0;
                *(uint32_t*)((char*)outh + ((size_t)(row + 8) * 4096 + col) * 2) = ph1;
                *(uint32_t*)((char*)outl + ((size_t)(row + 8) * 4096 + col) * 2) = pl1;
            }
        }
    }
}

// ---------------- launch ----------------
extern "C" void kernel_launch(void* const* d_in, const int* in_sizes, int n_in,
                              void* d_out, int out_size) {
    const float* x      = (const float*)d_in[0];
    const float* W      = (const float*)d_in[1];
    const float* b      = (const float*)d_in[2];
    const float* downs  = (const float*)d_in[3];
    const float* ups    = (const float*)d_in[4];
    const float* mags   = (const float*)d_in[5];
    const float* scales = (const float*)d_in[6];
    float* out = (float*)d_out;

    __nv_bfloat16 *xh, *xl, *wh, *wl, *uh, *ul, *dh, *dl;
    cudaGetSymbolAddress((void**)&xh, g_xh);
    cudaGetSymbolAddress((void**)&xl, g_xl);
    cudaGetSymbolAddress((void**)&wh, g_wh);
    cudaGetSymbolAddress((void**)&wl, g_wl);
    cudaGetSymbolAddress((void**)&uh, g_uh);
    cudaGetSymbolAddress((void**)&ul, g_ul);
    cudaGetSymbolAddress((void**)&dh, g_dh);
    cudaGetSymbolAddress((void**)&dl, g_dl);

    cudaFuncSetAttribute(gemm_mma<0>, cudaFuncAttributeMaxDynamicSharedMemorySize, SMEM_BYTES);
    cudaFuncSetAttribute(gemm_mma<1>, cudaFuncAttributeMaxDynamicSharedMemorySize, SMEM_BYTES);

    // 1) prep
    build_u_split<<<(NTOT * KF) / 256, 256>>>(ups, mags, scales);
    split_downsT<<<dim3(KTOT / 32, KF / 32), 256>>>(downs);
    split_x<<<(size_t)MTOT * KTOT / 8 / 256, 256>>>(x);

    // 2) fold: Weff = W + Uh.dT_h + Uh.dT_l + Ul.dT_h  -> (wh, wl)
    gemm_mma<1><<<dim3(NTOT / BN, NTOT / BM), 512, SMEM_BYTES>>>(
        uh, ul, dh, dl, W, nullptr, wh, wl, KF);

    // 3) main: out = Xh.Wh + Xh.Wl + Xl.Wh + bias
    gemm_mma<0><<<dim3(NTOT / BN, MTOT / BM), 512, SMEM_BYTES>>>(
        xh, xl, wh, wl, b, out, nullptr, nullptr, KTOT);
}